// round 2
// baseline (speedup 1.0000x reference)
#include <cuda_runtime.h>

// SlidingKernelAttention: x(2,64,67,67), unfold k=4 -> 2048 independent
// attention problems of [seq=256, d=16], then overlap-add fold.
//
// Kernel 1 (attn): 1 CTA per problem, 1 thread per query row.
//   - K/V rows in smem, broadcast LDS.128 in the key loop
//   - packed fma.rn.f32x2 for the dot and the AV accumulate (2x fp32 tput)
//   - one-pass softmax (no max subtraction; scores are O(1) by construction)
//   - writes ao rows to __device__ scratch g_ao[n][l], l = ph*64+pw
// Kernel 2 (fold): gather 16 taps per output pixel (deterministic, no atomics,
//   writes every output element -> no pre-zeroing needed).

#define DIM   16
#define HW    67
#define HOWO  64
#define SEQ   256
#define LTILE 4096          // 64*64
#define MAXPROB 2048        // B*C*16 for the bench shapes

__device__ float g_ao[(size_t)MAXPROB * LTILE];   // 33.5 MB scratch

typedef unsigned long long u64;

__device__ __forceinline__ u64 fma2(u64 a, u64 b, u64 c) {
    u64 d;
    asm("fma.rn.f32x2 %0, %1, %2, %3;" : "=l"(d) : "l"(a), "l"(b), "l"(c));
    return d;
}
__device__ __forceinline__ u64 pack2(float lo, float hi) {
    u64 r;
    asm("mov.b64 %0, {%1, %2};"
        : "=l"(r) : "r"(__float_as_uint(lo)), "r"(__float_as_uint(hi)));
    return r;
}
__device__ __forceinline__ void unpack2(u64 v, float& lo, float& hi) {
    unsigned ulo, uhi;
    asm("mov.b64 {%0, %1}, %2;" : "=r"(ulo), "=r"(uhi) : "l"(v));
    lo = __uint_as_float(ulo);
    hi = __uint_as_float(uhi);
}
__device__ __forceinline__ float ex2(float x) {
    float r;
    asm("ex2.approx.ftz.f32 %0, %1;" : "=f"(r) : "f"(x));
    return r;
}

__global__ __launch_bounds__(256)
void attn_kernel(const float* __restrict__ x, const float* __restrict__ wqkv) {
    __shared__ __align__(16) float s_w[48 * DIM];     // 3 KB
    __shared__ __align__(16) float s_k[SEQ][DIM];     // 16 KB
    __shared__ __align__(16) float s_v[SEQ][DIM];     // 16 KB

    const int n  = blockIdx.x;
    const int bc = n >> 4;
    const int p  = n & 15;
    const int pi = p >> 2;
    const int pj = p & 3;
    const int t  = threadIdx.x;          // query row s = t

    // weights -> smem
    for (int r = t; r < 48 * DIM; r += 256) s_w[r] = wqkv[r];

    // this thread's xu row: contiguous 16 floats of one x row
    const float* xp = x + (size_t)bc * (HW * HW)
                        + ((t >> 2) + pi) * HW + (t & 3) * DIM + pj;
    float xr[DIM];
#pragma unroll
    for (int e = 0; e < DIM; e++) xr[e] = xp[e];

    __syncthreads();

    // qkv projection (weights read broadcast from smem)
    float q[DIM], kr[DIM], vr[DIM];
#pragma unroll
    for (int d = 0; d < DIM; d++) {
        float aq = 0.f, ak = 0.f, av = 0.f;
#pragma unroll
        for (int e = 0; e < DIM; e++) {
            const float xe = xr[e];
            aq += xe * s_w[d * DIM + e];
            ak += xe * s_w[(DIM + d) * DIM + e];
            av += xe * s_w[(2 * DIM + d) * DIM + e];
        }
        q[d] = aq; kr[d] = ak; vr[d] = av;
    }

    // store K/V rows vectorized (4-way conflicts on store only; loads are broadcast)
    float4* kdst = (float4*)&s_k[t][0];
    float4* vdst = (float4*)&s_v[t][0];
#pragma unroll
    for (int c = 0; c < 4; c++) {
        kdst[c] = make_float4(kr[4*c], kr[4*c+1], kr[4*c+2], kr[4*c+3]);
        vdst[c] = make_float4(vr[4*c], vr[4*c+1], vr[4*c+2], vr[4*c+3]);
    }
    __syncthreads();

    // pack q into f32x2 pairs
    u64 q2[8];
#pragma unroll
    for (int c = 0; c < 8; c++) q2[c] = pack2(q[2*c], q[2*c+1]);

    u64 o2[8];
#pragma unroll
    for (int c = 0; c < 8; c++) o2[c] = 0ull;
    float lsum = 0.f;

    // exp(dot * SCALE) = exp2(dot * SCALE * log2(e)); SCALE = 2^-0.5
    const float cexp = (float)(1.4426950408889634 * 0.7071067811865476);

#pragma unroll 4
    for (int s2 = 0; s2 < SEQ; s2++) {
        const ulonglong2* krow = (const ulonglong2*)&s_k[s2][0];
        ulonglong2 ka = krow[0], kb = krow[1], kc = krow[2], kd = krow[3];
        u64 acca = 0ull, accb = 0ull;
        acca = fma2(q2[0], ka.x, acca);  accb = fma2(q2[1], ka.y, accb);
        acca = fma2(q2[2], kb.x, acca);  accb = fma2(q2[3], kb.y, accb);
        acca = fma2(q2[4], kc.x, acca);  accb = fma2(q2[5], kc.y, accb);
        acca = fma2(q2[6], kd.x, acca);  accb = fma2(q2[7], kd.y, accb);
        float a0, a1, b0, b1;
        unpack2(acca, a0, a1);
        unpack2(accb, b0, b1);
        const float e = ex2(((a0 + a1) + (b0 + b1)) * cexp);
        lsum += e;
        const u64 e2 = pack2(e, e);
        const ulonglong2* vrow = (const ulonglong2*)&s_v[s2][0];
        ulonglong2 va = vrow[0], vb = vrow[1], vc = vrow[2], vd = vrow[3];
        o2[0] = fma2(e2, va.x, o2[0]);  o2[1] = fma2(e2, va.y, o2[1]);
        o2[2] = fma2(e2, vb.x, o2[2]);  o2[3] = fma2(e2, vb.y, o2[3]);
        o2[4] = fma2(e2, vc.x, o2[4]);  o2[5] = fma2(e2, vc.y, o2[5]);
        o2[6] = fma2(e2, vd.x, o2[6]);  o2[7] = fma2(e2, vd.y, o2[7]);
    }

    const float inv = 1.0f / lsum;
    float o[DIM];
#pragma unroll
    for (int c = 0; c < 8; c++) unpack2(o2[c], o[2*c], o[2*c+1]);

    float4* dst = (float4*)(g_ao + (size_t)n * LTILE + t * DIM);
#pragma unroll
    for (int c = 0; c < 4; c++)
        dst[c] = make_float4(o[4*c] * inv, o[4*c+1] * inv,
                             o[4*c+2] * inv, o[4*c+3] * inv);
}

__global__ void fold_kernel(float* __restrict__ out, int total) {
    const int idx = blockIdx.x * blockDim.x + threadIdx.x;
    if (idx >= total) return;
    const int w   = idx % HW;
    const int rem = idx / HW;
    const int h   = rem % HW;
    const int bc  = rem / HW;
    const float* base = g_ao + (size_t)bc * 16 * LTILE;
    float acc = 0.f;
#pragma unroll
    for (int i = 0; i < 4; i++) {
        const int ph = h - i;
        if (ph < 0 || ph >= HOWO) continue;
#pragma unroll
        for (int j = 0; j < 4; j++) {
            const int pw = w - j;
            if (pw < 0 || pw >= HOWO) continue;
            acc += base[(i * 4 + j) * LTILE + ph * HOWO + pw];
        }
    }
    out[idx] = acc;
}

extern "C" void kernel_launch(void* const* d_in, const int* in_sizes, int n_in,
                              void* d_out, int out_size) {
    const float* x = (const float*)d_in[0];
    const float* w = (const float*)d_in[1];
    float* out = (float*)d_out;

    const int bc_count = in_sizes[0] / (HW * HW);     // B*C = 128
    const int nprob    = bc_count * 16;               // 2048
    const int total    = in_sizes[0];                 // 574592

    attn_kernel<<<nprob, 256>>>(x, w);
    fold_kernel<<<(total + 255) / 256, 256>>>(out, total);
}

// round 5
// speedup vs baseline: 1.8951x; 1.8951x over previous
#include <cuda_runtime.h>
#include <cstdint>

#define HW    67
#define HWHW  4489
#define LTILE 4096

__device__ float g_ao[(size_t)2048 * LTILE];   // 33.5 MB ao scratch

// ---- helpers ----
__device__ __forceinline__ float tf32f(float f) {
    uint32_t r; asm("cvt.rna.tf32.f32 %0, %1;" : "=r"(r) : "f"(f));
    return __uint_as_float(r);
}
__device__ __forceinline__ float ex2f(float x) {
    float r; asm("ex2.approx.ftz.f32 %0, %1;" : "=f"(r) : "f"(x));
    return r;
}
// D += A(16x8,tf32) * B(8x8,tf32), fp32 accum
__device__ __forceinline__ void mma8(float* d, const uint32_t* a, const uint32_t* b) {
    asm volatile("mma.sync.aligned.m16n8k8.row.col.f32.tf32.tf32.f32 "
                 "{%0,%1,%2,%3}, {%4,%5,%6,%7}, {%8,%9}, {%0,%1,%2,%3};"
                 : "+f"(d[0]), "+f"(d[1]), "+f"(d[2]), "+f"(d[3])
                 : "r"(a[0]), "r"(a[1]), "r"(a[2]), "r"(a[3]),
                   "r"(b[0]), "r"(b[1]));
}

// smem word offsets (dynamic, 21504 words = 86016 B)
#define O_P   0        // P buffer [256][36] = 9216 words, ALIASES QH/QL/W/G
#define O_QH  0        // 256*16 = 4096
#define O_QL  4096     // 4096
#define O_W   8192     // 768
#define O_G   8960     // 256
#define O_KT  9216     // kk^T frag layout [32][16][8] = 4096
#define O_VH  13312    // v^T hi frag layout [32][16][8] = 4096
#define O_VL  17408    // v^T lo = 4096
#define SMEM_BYTES (21504 * 4)

__global__ __launch_bounds__(256, 2)
void attn_mma_kernel(const float* __restrict__ x, const float* __restrict__ wqkv) {
    extern __shared__ float sm[];
    const int t    = threadIdx.x;
    const int lane = t & 31;
    const int w    = t >> 5;
    const int n  = blockIdx.x;
    const int bc = n >> 4;
    const int p  = n & 15;
    const int pi = p >> 2;
    const int pj = p & 3;

    // ---- prep: weights, G = Wq^T Wk ----
    for (int i = t; i < 768; i += 256) sm[O_W + i] = wqkv[i];

    // this thread's xu row (contiguous 16 floats of one x row)
    const float* xp = x + (size_t)bc * HWHW + ((t >> 2) + pi) * HW + (t & 3) * 16 + pj;
    float xr[16];
#pragma unroll
    for (int e = 0; e < 16; e++) xr[e] = xp[e];

    __syncthreads();
    {
        const int a = t >> 4, b = t & 15;
        float s = 0.f;
#pragma unroll
        for (int d = 0; d < 16; d++)
            s += sm[O_W + d * 16 + a] * sm[O_W + (16 + d) * 16 + b];
        sm[O_G + t] = s;
    }
    __syncthreads();

    // q hi/lo (raw x, split for 2-pass tf32)
#pragma unroll
    for (int e = 0; e < 16; e++) {
        float h = tf32f(xr[e]);
        sm[O_QH + t * 16 + e] = h;
        sm[O_QL + t * 16 + e] = tf32f(xr[e] - h);
    }
    // kk = G x  -> B-fragment layout [key/8][d][key%8]
    {
        const int tb = O_KT + (t >> 3) * 128 + (t & 7);
#pragma unroll
        for (int a = 0; a < 16; a++) {
            float s = 0.f;
#pragma unroll
            for (int b = 0; b < 16; b++) s += sm[O_G + a * 16 + b] * xr[b];
            sm[tb + a * 8] = tf32f(s);
        }
    }
    // v = Wv x, hi/lo -> B-fragment layout
    {
        const int tb = (t >> 3) * 128 + (t & 7);
#pragma unroll
        for (int d = 0; d < 16; d++) {
            float s = 0.f;
#pragma unroll
            for (int e = 0; e < 16; e++) s += sm[O_W + (32 + d) * 16 + e] * xr[e];
            float h = tf32f(s);
            sm[O_VH + tb + d * 8] = h;
            sm[O_VL + tb + d * 8] = tf32f(s - h);
        }
    }
    __syncthreads();

    // ---- load A (query) fragments once: hi and lo ----
    uint32_t aqh[2][2][4], aql[2][2][4];
#pragma unroll
    for (int mt = 0; mt < 2; mt++)
#pragma unroll
        for (int kt = 0; kt < 2; kt++) {
            const int base = (w * 32 + mt * 16 + (lane >> 2)) * 16 + kt * 8 + (lane & 3);
            aqh[mt][kt][0] = __float_as_uint(sm[O_QH + base]);
            aqh[mt][kt][1] = __float_as_uint(sm[O_QH + base + 128]);
            aqh[mt][kt][2] = __float_as_uint(sm[O_QH + base + 4]);
            aqh[mt][kt][3] = __float_as_uint(sm[O_QH + base + 132]);
            aql[mt][kt][0] = __float_as_uint(sm[O_QL + base]);
            aql[mt][kt][1] = __float_as_uint(sm[O_QL + base + 128]);
            aql[mt][kt][2] = __float_as_uint(sm[O_QL + base + 4]);
            aql[mt][kt][3] = __float_as_uint(sm[O_QL + base + 132]);
        }
    __syncthreads();   // Q region now reusable as P buffer

    const float CEXP = 1.0202976513f;   // log2(e) * (DIM/HEADS)^-0.5
    float o[2][2][4];
#pragma unroll
    for (int a = 0; a < 2; a++)
#pragma unroll
        for (int b = 0; b < 2; b++)
#pragma unroll
            for (int c = 0; c < 4; c++) o[a][b][c] = 0.f;
    float ls[2][2] = {0.f, 0.f, 0.f, 0.f};
    const int prow = w * 32 + (lane >> 2);

    for (int ch = 0; ch < 8; ch++) {
        __syncwarp();                    // P buffer reuse across chunks
        float s[2][4][4];
#pragma unroll
        for (int a = 0; a < 2; a++)
#pragma unroll
            for (int b = 0; b < 4; b++)
#pragma unroll
                for (int c = 0; c < 4; c++) s[a][b][c] = 0.f;

        // S = (x_hi + x_lo) . kk^T   (2-pass tf32)
#pragma unroll
        for (int nt = 0; nt < 4; nt++) {
            const int T = ch * 4 + nt;
            uint32_t bk[2][2];
#pragma unroll
            for (int kt = 0; kt < 2; kt++) {
                const int fl = O_KT + T * 128 + (kt * 8 + (lane & 3)) * 8 + (lane >> 2);
                bk[kt][0] = __float_as_uint(sm[fl]);
                bk[kt][1] = __float_as_uint(sm[fl + 32]);
            }
#pragma unroll
            for (int mt = 0; mt < 2; mt++)
#pragma unroll
                for (int kt = 0; kt < 2; kt++) {
                    mma8(s[mt][nt], aqh[mt][kt], bk[kt]);
                    mma8(s[mt][nt], aql[mt][kt], bk[kt]);
                }
        }

        // exp + store P (tf32-rounded) to per-warp rows of P buffer
#pragma unroll
        for (int mt = 0; mt < 2; mt++) {
            const int rb = (prow + mt * 16) * 36 + 2 * (lane & 3);
#pragma unroll
            for (int nt = 0; nt < 4; nt++) {
                float p0 = tf32f(ex2f(s[mt][nt][0] * CEXP));
                float p1 = tf32f(ex2f(s[mt][nt][1] * CEXP));
                float p2 = tf32f(ex2f(s[mt][nt][2] * CEXP));
                float p3 = tf32f(ex2f(s[mt][nt][3] * CEXP));
                ls[mt][0] += p0 + p1;
                ls[mt][1] += p2 + p3;
                *(float2*)&sm[rb + nt * 8]       = make_float2(p0, p1);
                *(float2*)&sm[rb + nt * 8 + 288] = make_float2(p2, p3);
            }
        }
        __syncwarp();

        // O += P . (v_hi + v_lo)^T   (2-pass tf32)
#pragma unroll
        for (int j = 0; j < 4; j++) {
            const int T = ch * 4 + j;
            uint32_t ap[2][4];
#pragma unroll
            for (int mt = 0; mt < 2; mt++) {
                const int base = (prow + mt * 16) * 36 + j * 8 + (lane & 3);
                ap[mt][0] = __float_as_uint(sm[base]);
                ap[mt][1] = __float_as_uint(sm[base + 288]);
                ap[mt][2] = __float_as_uint(sm[base + 4]);
                ap[mt][3] = __float_as_uint(sm[base + 292]);
            }
#pragma unroll
            for (int nt = 0; nt < 2; nt++) {
                const int fl = T * 128 + (nt * 8 + (lane >> 2)) * 8 + (lane & 3);
                uint32_t bh[2] = {__float_as_uint(sm[O_VH + fl]),
                                  __float_as_uint(sm[O_VH + fl + 4])};
                uint32_t bl[2] = {__float_as_uint(sm[O_VL + fl]),
                                  __float_as_uint(sm[O_VL + fl + 4])};
#pragma unroll
                for (int mt = 0; mt < 2; mt++) {
                    mma8(o[mt][nt], ap[mt], bh);
                    mma8(o[mt][nt], ap[mt], bl);
                }
            }
        }
    }

    // ---- epilogue: row sums across the 4 lanes sharing a row, divide, store ----
#pragma unroll
    for (int mt = 0; mt < 2; mt++)
#pragma unroll
        for (int h = 0; h < 2; h++) {
            float l = ls[mt][h];
            l += __shfl_xor_sync(0xffffffffu, l, 1);
            l += __shfl_xor_sync(0xffffffffu, l, 2);
            ls[mt][h] = 1.0f / l;
        }
    float* dst = g_ao + (size_t)n * LTILE;
#pragma unroll
    for (int mt = 0; mt < 2; mt++) {
        const int r0 = w * 32 + mt * 16 + (lane >> 2);
#pragma unroll
        for (int nt = 0; nt < 2; nt++) {
            const int d0 = nt * 8 + 2 * (lane & 3);
            *(float2*)&dst[r0 * 16 + d0] =
                make_float2(o[mt][nt][0] * ls[mt][0], o[mt][nt][1] * ls[mt][0]);
            *(float2*)&dst[(r0 + 8) * 16 + d0] =
                make_float2(o[mt][nt][2] * ls[mt][1], o[mt][nt][3] * ls[mt][1]);
        }
    }
}

__global__ void fold_kernel(float* __restrict__ out, int total) {
    const int idx = blockIdx.x * blockDim.x + threadIdx.x;
    if (idx >= total) return;
    const int w   = idx % HW;
    const int rem = idx / HW;
    const int h   = rem % HW;
    const int bc  = rem / HW;
    const float* bsrc = g_ao + (size_t)bc * 16 * LTILE;
    float acc = 0.f;
#pragma unroll
    for (int i = 0; i < 4; i++) {
        const int ph = h - i;
        if (ph < 0 || ph >= 64) continue;
#pragma unroll
        for (int j = 0; j < 4; j++) {
            const int pw = w - j;
            if (pw < 0 || pw >= 64) continue;
            acc += bsrc[(i * 4 + j) * LTILE + ph * 64 + pw];
        }
    }
    out[idx] = acc;
}

extern "C" void kernel_launch(void* const* d_in, const int* in_sizes, int n_in,
                              void* d_out, int out_size) {
    const float* x = (const float*)d_in[0];
    const float* w = (const float*)d_in[1];
    float* out = (float*)d_out;

    const int bc_count = in_sizes[0] / HWHW;      // B*C = 128
    const int nprob    = bc_count * 16;           // 2048
    const int total    = in_sizes[0];

    cudaFuncSetAttribute(attn_mma_kernel,
                         cudaFuncAttributeMaxDynamicSharedMemorySize, SMEM_BYTES);
    attn_mma_kernel<<<nprob, 256, SMEM_BYTES>>>(x, w);
    fold_kernel<<<(total + 255) / 256, 256>>>(out, total);
}

// round 7
// speedup vs baseline: 2.7786x; 1.4662x over previous
#include <cuda_runtime.h>
#include <cstdint>

#define HW    67
#define HWHW  4489
#define LTILE 4096

__device__ float g_ao[(size_t)2048 * LTILE];   // 33.5 MB ao scratch

__device__ __forceinline__ float tf32f(float f) {
    uint32_t r; asm("cvt.rna.tf32.f32 %0, %1;" : "=r"(r) : "f"(f));
    return __uint_as_float(r);
}
__device__ __forceinline__ float ex2f(float x) {
    float r; asm("ex2.approx.ftz.f32 %0, %1;" : "=f"(r) : "f"(x));
    return r;
}
__device__ __forceinline__ void mma8(float* d, const uint32_t* a, const uint32_t* b) {
    asm volatile("mma.sync.aligned.m16n8k8.row.col.f32.tf32.tf32.f32 "
                 "{%0,%1,%2,%3}, {%4,%5,%6,%7}, {%8,%9}, {%0,%1,%2,%3};"
                 : "+f"(d[0]), "+f"(d[1]), "+f"(d[2]), "+f"(d[3])
                 : "r"(a[0]), "r"(a[1]), "r"(a[2]), "r"(a[3]),
                   "r"(b[0]), "r"(b[1]));
}

// smem word offsets (17408 words = 69632 B)
#define O_P   0        // P buffer [256][36] = 9216 words (aliases X/W/G)
#define O_X   0        // raw x rows, stride 20 -> 5120 words
#define O_W   5120     // 768
#define O_GH  5888     // 256
#define O_GL  6144     // 256
#define O_KT  9216     // kk frag layout [keytile32][d16][key%8] = 4096
#define O_VT  13312    // v  frag layout [keytile32][d16][key%8] = 4096
#define SMEM_BYTES (17408 * 4)

__global__ __launch_bounds__(256, 3)
void attn_mma_kernel(const float* __restrict__ x, const float* __restrict__ wqkv) {
    extern __shared__ float sm[];
    const int t    = threadIdx.x;
    const int lane = t & 31;
    const int w    = t >> 5;
    const int gr   = lane >> 2;
    const int gc   = lane & 3;
    const int n  = blockIdx.x;
    const int bc = n >> 4;
    const int p  = n & 15;
    const int pi = p >> 2;
    const int pj = p & 3;

    // ---- stage weights + raw x rows ----
    for (int i = t; i < 768; i += 256) sm[O_W + i] = wqkv[i];
    {
        const float* xp = x + (size_t)bc * HWHW + ((t >> 2) + pi) * HW + (t & 3) * 16 + pj;
        float xr[16];
#pragma unroll
        for (int e = 0; e < 16; e++) xr[e] = xp[e];
#pragma unroll
        for (int c = 0; c < 4; c++)
            *(float4*)&sm[O_X + t * 20 + 4 * c] =
                make_float4(xr[4*c], xr[4*c+1], xr[4*c+2], xr[4*c+3]);
    }
    __syncthreads();

    // ---- G = Wq^T Wk, split hi/lo ----
    {
        const int a = t >> 4, b = t & 15;
        float s = 0.f;
#pragma unroll
        for (int d = 0; d < 16; d++)
            s += sm[O_W + d * 16 + a] * sm[O_W + (16 + d) * 16 + b];
        float h = tf32f(s);
        sm[O_GH + t] = h;
        sm[O_GL + t] = tf32f(s - h);
    }
    __syncthreads();

    // ---- A-fragments of raw x (hi/lo) ----
    uint32_t aqh[2][2][4], aql[2][2][4];
#pragma unroll
    for (int mt = 0; mt < 2; mt++)
#pragma unroll
        for (int kt = 0; kt < 2; kt++) {
            const int rb = O_X + (w * 32 + mt * 16 + gr) * 20 + kt * 8 + gc;
            float r0 = sm[rb], r1 = sm[rb + 160], r2 = sm[rb + 4], r3 = sm[rb + 164];
            float h0 = tf32f(r0), h1 = tf32f(r1), h2 = tf32f(r2), h3 = tf32f(r3);
            aqh[mt][kt][0] = __float_as_uint(h0);
            aqh[mt][kt][1] = __float_as_uint(h1);
            aqh[mt][kt][2] = __float_as_uint(h2);
            aqh[mt][kt][3] = __float_as_uint(h3);
            aql[mt][kt][0] = __float_as_uint(tf32f(r0 - h0));
            aql[mt][kt][1] = __float_as_uint(tf32f(r1 - h1));
            aql[mt][kt][2] = __float_as_uint(tf32f(r2 - h2));
            aql[mt][kt][3] = __float_as_uint(tf32f(r3 - h3));
        }

    // ---- kk = x @ G^T (3-pass), store to KT frag layout ----
    {
        uint32_t gh[2][2][2], gl[2][2][2];
#pragma unroll
        for (int nt = 0; nt < 2; nt++)
#pragma unroll
            for (int kt = 0; kt < 2; kt++)
#pragma unroll
                for (int r = 0; r < 2; r++) {
                    const int idx = (nt * 8 + gr) * 16 + kt * 8 + gc + 4 * r;
                    gh[nt][kt][r] = __float_as_uint(sm[O_GH + idx]);
                    gl[nt][kt][r] = __float_as_uint(sm[O_GL + idx]);
                }
        float acc[2][2][4];
#pragma unroll
        for (int a = 0; a < 2; a++)
#pragma unroll
            for (int b = 0; b < 2; b++)
#pragma unroll
                for (int c = 0; c < 4; c++) acc[a][b][c] = 0.f;
#pragma unroll
        for (int mt = 0; mt < 2; mt++)
#pragma unroll
            for (int nt = 0; nt < 2; nt++)
#pragma unroll
                for (int kt = 0; kt < 2; kt++) {
                    mma8(acc[mt][nt], aqh[mt][kt], gh[nt][kt]);
                    mma8(acc[mt][nt], aql[mt][kt], gh[nt][kt]);
                    mma8(acc[mt][nt], aqh[mt][kt], gl[nt][kt]);
                }
        // wv fragments (hi/lo from raw weights)
        uint32_t wh[2][2][2], wl[2][2][2];
#pragma unroll
        for (int nt = 0; nt < 2; nt++)
#pragma unroll
            for (int kt = 0; kt < 2; kt++)
#pragma unroll
                for (int r = 0; r < 2; r++) {
                    float wv = sm[O_W + (32 + nt * 8 + gr) * 16 + kt * 8 + gc + 4 * r];
                    float h = tf32f(wv);
                    wh[nt][kt][r] = __float_as_uint(h);
                    wl[nt][kt][r] = __float_as_uint(tf32f(wv - h));
                }
        // store kk (must finish G/X reads? KT/VT regions are disjoint from X/W/G - safe)
#pragma unroll
        for (int mt = 0; mt < 2; mt++)
#pragma unroll
            for (int nt = 0; nt < 2; nt++) {
                const int r = w * 32 + mt * 16 + gr;
                const int base = O_KT + (r >> 3) * 128 + (nt * 8 + 2 * gc) * 8 + gr;
                sm[base]       = tf32f(acc[mt][nt][0]);
                sm[base + 8]   = tf32f(acc[mt][nt][1]);
                sm[base + 128] = tf32f(acc[mt][nt][2]);
                sm[base + 136] = tf32f(acc[mt][nt][3]);
            }
        // ---- v = x @ Wv^T (3-pass), store to VT ----
#pragma unroll
        for (int a = 0; a < 2; a++)
#pragma unroll
            for (int b = 0; b < 2; b++)
#pragma unroll
                for (int c = 0; c < 4; c++) acc[a][b][c] = 0.f;
#pragma unroll
        for (int mt = 0; mt < 2; mt++)
#pragma unroll
            for (int nt = 0; nt < 2; nt++)
#pragma unroll
                for (int kt = 0; kt < 2; kt++) {
                    mma8(acc[mt][nt], aqh[mt][kt], wh[nt][kt]);
                    mma8(acc[mt][nt], aql[mt][kt], wh[nt][kt]);
                    mma8(acc[mt][nt], aqh[mt][kt], wl[nt][kt]);
                }
#pragma unroll
        for (int mt = 0; mt < 2; mt++)
#pragma unroll
            for (int nt = 0; nt < 2; nt++) {
                const int r = w * 32 + mt * 16 + gr;
                const int base = O_VT + (r >> 3) * 128 + (nt * 8 + 2 * gc) * 8 + gr;
                sm[base]       = tf32f(acc[mt][nt][0]);
                sm[base + 8]   = tf32f(acc[mt][nt][1]);
                sm[base + 128] = tf32f(acc[mt][nt][2]);
                sm[base + 136] = tf32f(acc[mt][nt][3]);
            }
    }
    __syncthreads();   // KT/VT ready; X/W/G dead -> P region free

    // ---- mainloop ----
    const float CEXP = 1.0202976513f;   // log2(e) * 2^-0.5
    float o[2][2][4];
#pragma unroll
    for (int a = 0; a < 2; a++)
#pragma unroll
        for (int b = 0; b < 2; b++)
#pragma unroll
            for (int c = 0; c < 4; c++) o[a][b][c] = 0.f;
    float ls[2][2] = {0.f, 0.f, 0.f, 0.f};
    const int prow = w * 32 + gr;

    for (int ch = 0; ch < 8; ch++) {
#pragma unroll
        for (int hh = 0; hh < 2; hh++) {
            float s[2][2][4];
#pragma unroll
            for (int a = 0; a < 2; a++)
#pragma unroll
                for (int b = 0; b < 2; b++)
#pragma unroll
                    for (int c = 0; c < 4; c++) s[a][b][c] = 0.f;
            uint32_t bk[2][2][2];
#pragma unroll
            for (int ntl = 0; ntl < 2; ntl++) {
                const int T = ch * 4 + hh * 2 + ntl;
#pragma unroll
                for (int kt = 0; kt < 2; kt++) {
                    const int fl = O_KT + T * 128 + (kt * 8 + gc) * 8 + gr;
                    bk[ntl][kt][0] = __float_as_uint(sm[fl]);
                    bk[ntl][kt][1] = __float_as_uint(sm[fl + 32]);
                }
            }
#pragma unroll
            for (int ntl = 0; ntl < 2; ntl++)
#pragma unroll
                for (int mt = 0; mt < 2; mt++)
#pragma unroll
                    for (int kt = 0; kt < 2; kt++) {
                        mma8(s[mt][ntl], aqh[mt][kt], bk[ntl][kt]);
                        mma8(s[mt][ntl], aql[mt][kt], bk[ntl][kt]);
                    }
#pragma unroll
            for (int mt = 0; mt < 2; mt++) {
                const int rb = (prow + mt * 16) * 36 + 2 * gc;
#pragma unroll
                for (int ntl = 0; ntl < 2; ntl++) {
                    const int nt = hh * 2 + ntl;
                    float p0 = tf32f(ex2f(s[mt][ntl][0] * CEXP));
                    float p1 = tf32f(ex2f(s[mt][ntl][1] * CEXP));
                    float p2 = tf32f(ex2f(s[mt][ntl][2] * CEXP));
                    float p3 = tf32f(ex2f(s[mt][ntl][3] * CEXP));
                    ls[mt][0] += p0 + p1;
                    ls[mt][1] += p2 + p3;
                    *(float2*)&sm[rb + nt * 8]       = make_float2(p0, p1);
                    *(float2*)&sm[rb + nt * 8 + 288] = make_float2(p2, p3);
                }
            }
        }
        __syncwarp();

#pragma unroll
        for (int j = 0; j < 4; j++) {
            const int T = ch * 4 + j;
            uint32_t ap[2][4];
#pragma unroll
            for (int mt = 0; mt < 2; mt++) {
                const int base = (prow + mt * 16) * 36 + j * 8 + gc;
                ap[mt][0] = __float_as_uint(sm[base]);
                ap[mt][1] = __float_as_uint(sm[base + 288]);
                ap[mt][2] = __float_as_uint(sm[base + 4]);
                ap[mt][3] = __float_as_uint(sm[base + 292]);
            }
#pragma unroll
            for (int ntv = 0; ntv < 2; ntv++) {
                const int fl = O_VT + T * 128 + (ntv * 8 + gr) * 8 + gc;
                uint32_t bv[2] = {__float_as_uint(sm[fl]),
                                  __float_as_uint(sm[fl + 4])};
#pragma unroll
                for (int mt = 0; mt < 2; mt++)
                    mma8(o[mt][ntv], ap[mt], bv);
            }
        }
        __syncwarp();
    }

    // ---- epilogue ----
#pragma unroll
    for (int mt = 0; mt < 2; mt++)
#pragma unroll
        for (int h = 0; h < 2; h++) {
            float l = ls[mt][h];
            l += __shfl_xor_sync(0xffffffffu, l, 1);
            l += __shfl_xor_sync(0xffffffffu, l, 2);
            ls[mt][h] = 1.0f / l;
        }
    float* dst = g_ao + (size_t)n * LTILE;
#pragma unroll
    for (int mt = 0; mt < 2; mt++) {
        const int r0 = w * 32 + mt * 16 + gr;
#pragma unroll
        for (int ntv = 0; ntv < 2; ntv++) {
            const int d0 = ntv * 8 + 2 * gc;
            *(float2*)&dst[r0 * 16 + d0] =
                make_float2(o[mt][ntv][0] * ls[mt][0], o[mt][ntv][1] * ls[mt][0]);
            *(float2*)&dst[(r0 + 8) * 16 + d0] =
                make_float2(o[mt][ntv][2] * ls[mt][1], o[mt][ntv][3] * ls[mt][1]);
        }
    }
}

__global__ void fold_kernel(float* __restrict__ out, int total) {
    const int idx = blockIdx.x * blockDim.x + threadIdx.x;
    if (idx >= total) return;
    const int w   = idx % HW;
    const int rem = idx / HW;
    const int h   = rem % HW;
    const int bc  = rem / HW;
    const float* bsrc = g_ao + (size_t)bc * 16 * LTILE;
    float acc = 0.f;
#pragma unroll
    for (int i = 0; i < 4; i++) {
        const int ph = h - i;
        if (ph < 0 || ph >= 64) continue;
#pragma unroll
        for (int j = 0; j < 4; j++) {
            const int pw = w - j;
            if (pw < 0 || pw >= 64) continue;
            acc += bsrc[(i * 4 + j) * LTILE + ph * 64 + pw];
        }
    }
    out[idx] = acc;
}

extern "C" void kernel_launch(void* const* d_in, const int* in_sizes, int n_in,
                              void* d_out, int out_size) {
    const float* x = (const float*)d_in[0];
    const float* w = (const float*)d_in[1];
    float* out = (float*)d_out;

    const int bc_count = in_sizes[0] / HWHW;      // B*C = 128
    const int nprob    = bc_count * 16;           // 2048
    const int total    = in_sizes[0];

    cudaFuncSetAttribute(attn_mma_kernel,
                         cudaFuncAttributeMaxDynamicSharedMemorySize, SMEM_BYTES);
    attn_mma_kernel<<<nprob, 256, SMEM_BYTES>>>(x, w);
    fold_kernel<<<(total + 255) / 256, 256>>>(out, total);
}